// round 1
// baseline (speedup 1.0000x reference)
#include <cuda_runtime.h>
#include <cuda_fp16.h>
#include <mma.h>

using namespace nvcuda;

// Problem constants
#define NTOK   131072          // B*S = 32*4096
#define DIM    1024
#define BATCH  32
#define SEQ    4096
#define NROWT  (NTOK/128)      // 1024 row tiles
#define NCOLT  (DIM/128)       // 8 col tiles
#define NBLOCKS (NROWT*NCOLT)  // 8192

// ---------------- device scratch (allowed per harness rules) ----------------
__device__ __half g_A  [1024*1024];            // logits weights: wq_h @ kv_h^T
__device__ __half g_Bm [1024*1024];            // kv_h @ wo_h  (attn->out@wo)
__device__ __half g_w1h[1024*1024];
__device__ __half g_w2h[1024*1024];
__device__ __half g_P  [(size_t)NTOK*1024];    // softmax probs (256MB)
__device__ __half g_U  [(size_t)NTOK*1024];    // out@wo       (256MB)
__device__ __half g_H  [(size_t)NTOK*1024];    // gelu hidden  (256MB)

// ---------------- helpers ----------------
__global__ void zero_out_kernel(float* o, int n) {
    int i = blockIdx.x * 256 + threadIdx.x;
    if (i < n) o[i] = 0.0f;
}

// A[d, h*64+r] = sum_j wq[d, h*64+j] * kv[r, h*64+j]
__global__ void prep_A_kernel(const float* __restrict__ wq,
                              const float* __restrict__ kv) {
    __shared__ float wq_s[64][65];
    __shared__ float kv_s[64][65];
    int h  = blockIdx.x;   // head
    int dt = blockIdx.y;   // d tile (64 rows)
    int t  = threadIdx.x;
    #pragma unroll
    for (int e = 0; e < 16; e++) {
        int lin = t + 256 * e;
        int r = lin >> 6, c = lin & 63;
        wq_s[r][c] = wq[(size_t)(dt*64 + r)*1024 + h*64 + c];
        kv_s[r][c] = kv[(size_t)r*1024 + h*64 + c];
    }
    __syncthreads();
    #pragma unroll
    for (int e = 0; e < 16; e++) {
        int lin = t + 256 * e;
        int i = lin >> 6, r = lin & 63;
        float s = 0.f;
        #pragma unroll
        for (int j = 0; j < 64; j++) s += wq_s[i][j] * kv_s[r][j];
        g_A[(size_t)(dt*64 + i)*1024 + h*64 + r] = __float2half_rn(s);
    }
}

// Bm[h*64+r, d] = sum_j kv[r, h*64+j] * wo[h*64+j, d]
__global__ void prep_B_kernel(const float* __restrict__ kv,
                              const float* __restrict__ wo) {
    __shared__ float kv_s[64][65];
    __shared__ float wo_s[64][65];
    int h  = blockIdx.x;
    int ct = blockIdx.y;   // d col tile
    int t  = threadIdx.x;
    #pragma unroll
    for (int e = 0; e < 16; e++) {
        int lin = t + 256 * e;
        int r = lin >> 6, c = lin & 63;
        kv_s[r][c] = kv[(size_t)r*1024 + h*64 + c];
        wo_s[r][c] = wo[(size_t)(h*64 + r)*1024 + ct*64 + c];
    }
    __syncthreads();
    #pragma unroll
    for (int e = 0; e < 16; e++) {
        int lin = t + 256 * e;
        int r = lin >> 6, d = lin & 63;
        float s = 0.f;
        #pragma unroll
        for (int j = 0; j < 64; j++) s += kv_s[r][j] * wo_s[j][d];
        g_Bm[(size_t)(h*64 + r)*1024 + ct*64 + d] = __float2half_rn(s);
    }
}

__global__ void conv_w_kernel(const float* __restrict__ w1,
                              const float* __restrict__ w2) {
    int i = blockIdx.x * 256 + threadIdx.x;   // grid covers 1M
    g_w1h[i] = __float2half_rn(w1[i]);
    g_w2h[i] = __float2half_rn(w2[i]);
}

// ---------------- fused GEMM ----------------
// C[128,128] tile of  A[NTOK,1024] @ W[1024,1024]  with per-MODE epilogue.
// MODE 0: A = x (fp32, converted on the fly), W = g_A.  Epilogue: *scale, block
//         softmax over 64-col head blocks -> g_P (fp16)
// MODE 1: A = g_P, W = g_Bm.  Epilogue: store fp16 -> g_U
// MODE 2: A = g_U, W = g_w1h. Epilogue: +b1, exact GELU -> g_H
// MODE 3: A = g_H, W = g_w2h. Epilogue: +b2 + U residual, column-sum partial
//         mean-pool atomically into out[32,1024]
template<int MODE, bool AF32>
__global__ void __launch_bounds__(256)
fused_gemm(const float* __restrict__ xin,
           const float* __restrict__ bias,
           float* __restrict__ outp) {
    extern __shared__ char smem[];
    __half* A_s = (__half*)smem;                 // 128 x 72 halves = 18432 B
    __half* W_s = (__half*)(smem + 18432);       //  64 x 136 halves = 17408 B
    float*  C_s = (float*)smem;                  // 128 x 132 floats = 67584 B (reuse)

    const void*   Aptr;
    const __half* Wg;
    if constexpr (MODE == 0)      { Aptr = xin; Wg = g_A;   }
    else if constexpr (MODE == 1) { Aptr = g_P; Wg = g_Bm;  }
    else if constexpr (MODE == 2) { Aptr = g_U; Wg = g_w1h; }
    else                          { Aptr = g_H; Wg = g_w2h; }

    int t    = threadIdx.x;
    int bid  = blockIdx.x;
    int rt   = bid >> 3;       // row tile (col-tile fastest -> L2 reuse of A rows)
    int ct   = bid & 7;
    int row0 = rt * 128;
    int n0   = ct * 128;
    int warp = t >> 5;
    int wm   = warp & 3;       // 4 warp rows of 32
    int wn   = warp >> 2;      // 2 warp cols of 64

    wmma::fragment<wmma::accumulator, 16, 16, 16, float> acc[2][4];
    #pragma unroll
    for (int mi = 0; mi < 2; mi++)
        #pragma unroll
        for (int ni = 0; ni < 4; ni++)
            wmma::fill_fragment(acc[mi][ni], 0.0f);

    for (int kc = 0; kc < 1024; kc += 64) {
        // ---- stage A tile [128 x 64] ----
        {
            int i  = t >> 1;
            int j0 = (t & 1) * 32;
            if constexpr (AF32) {
                const float* Ag = (const float*)Aptr + (size_t)(row0 + i)*1024 + kc + j0;
                __half* dst = A_s + i*72 + j0;
                #pragma unroll
                for (int l = 0; l < 8; l++) {
                    float4 v = *(const float4*)(Ag + l*4);
                    dst[l*4+0] = __float2half_rn(v.x);
                    dst[l*4+1] = __float2half_rn(v.y);
                    dst[l*4+2] = __float2half_rn(v.z);
                    dst[l*4+3] = __float2half_rn(v.w);
                }
            } else {
                const uint4* Ag = (const uint4*)((const __half*)Aptr +
                                     (size_t)(row0 + i)*1024 + kc + j0);
                uint4* dst = (uint4*)(A_s + i*72 + j0);
                #pragma unroll
                for (int l = 0; l < 4; l++) dst[l] = Ag[l];
            }
        }
        // ---- stage W tile [64 x 128] ----
        {
            #pragma unroll
            for (int u_it = 0; u_it < 4; u_it++) {
                int lin = t + 256 * u_it;
                int j = lin >> 4, u = lin & 15;
                uint4 v = *(const uint4*)(Wg + (size_t)(kc + j)*1024 + n0 + u*8);
                *(uint4*)(W_s + j*136 + u*8) = v;
            }
        }
        __syncthreads();
        #pragma unroll
        for (int kk = 0; kk < 64; kk += 16) {
            wmma::fragment<wmma::matrix_a, 16, 16, 16, __half, wmma::row_major> af[2];
            wmma::fragment<wmma::matrix_b, 16, 16, 16, __half, wmma::row_major> bf[4];
            #pragma unroll
            for (int mi = 0; mi < 2; mi++)
                wmma::load_matrix_sync(af[mi], A_s + (wm*32 + mi*16)*72 + kk, 72);
            #pragma unroll
            for (int ni = 0; ni < 4; ni++)
                wmma::load_matrix_sync(bf[ni], W_s + kk*136 + wn*64 + ni*16, 136);
            #pragma unroll
            for (int mi = 0; mi < 2; mi++)
                #pragma unroll
                for (int ni = 0; ni < 4; ni++)
                    wmma::mma_sync(acc[mi][ni], af[mi], bf[ni], acc[mi][ni]);
        }
        __syncthreads();
    }

    // ---- dump accumulators to SMEM (reuses staging buffers) ----
    #pragma unroll
    for (int mi = 0; mi < 2; mi++)
        #pragma unroll
        for (int ni = 0; ni < 4; ni++)
            wmma::store_matrix_sync(C_s + (wm*32 + mi*16)*132 + wn*64 + ni*16,
                                    acc[mi][ni], 132, wmma::mem_row_major);
    __syncthreads();

    // ---- epilogues ----
    if constexpr (MODE == 0) {
        // block softmax: each thread handles one (row, head) pair; head = 64 cols
        const float scale = 0.125f;                 // R^-0.5
        int row  = t >> 1;
        int head = t & 1;
        const float* rowp = C_s + row*132 + head*64;
        float m = -1e30f;
        #pragma unroll
        for (int j = 0; j < 64; j++) m = fmaxf(m, rowp[j] * scale);
        float s = 0.f;
        #pragma unroll
        for (int j = 0; j < 64; j++) s += __expf(rowp[j]*scale - m);
        float inv = 1.f / s;
        __half* op = g_P + (size_t)(row0 + row)*1024 + n0 + head*64;
        #pragma unroll
        for (int j = 0; j < 64; j += 8) {
            union { uint4 u4; __half2 h2[4]; } pk;
            #pragma unroll
            for (int q = 0; q < 4; q++) {
                float v0 = __expf(rowp[j + 2*q    ]*scale - m) * inv;
                float v1 = __expf(rowp[j + 2*q + 1]*scale - m) * inv;
                pk.h2[q] = __floats2half2_rn(v0, v1);
            }
            *(uint4*)(op + j) = pk.u4;
        }
    } else if constexpr (MODE == 1 || MODE == 2) {
        __half* dstbase = (MODE == 1) ? g_U : g_H;
        #pragma unroll
        for (int v = 0; v < 8; v++) {
            int lin = t + 256 * v;
            int i = lin >> 4, u = lin & 15;
            const float* src = C_s + i*132 + u*8;
            float vals[8];
            #pragma unroll
            for (int jj = 0; jj < 8; jj++) vals[jj] = src[jj];
            if constexpr (MODE == 2) {
                #pragma unroll
                for (int jj = 0; jj < 8; jj++) {
                    float z = vals[jj] + __ldg(bias + n0 + u*8 + jj);
                    vals[jj] = 0.5f * z * (1.0f + erff(z * 0.70710678118f));
                }
            }
            union { uint4 u4; __half2 h2[4]; } pk;
            #pragma unroll
            for (int q = 0; q < 4; q++)
                pk.h2[q] = __floats2half2_rn(vals[2*q], vals[2*q+1]);
            *(uint4*)(dstbase + (size_t)(row0 + i)*1024 + n0 + u*8) = pk.u4;
        }
    } else {
        // MODE 3: y = C + b2 + U residual; partial mean-pool over the 128 rows
        if (t < 128) {
            int gcol = n0 + t;
            float b2v = __ldg(bias + gcol);
            float s = 0.f;
            #pragma unroll 4
            for (int i = 0; i < 128; i++) {
                float u = __half2float(g_U[(size_t)(row0 + i)*1024 + gcol]);
                s += C_s[i*132 + t] + b2v + u;
            }
            int b = row0 >> 12;                    // / 4096 (tiles never straddle)
            atomicAdd(outp + b*1024 + gcol, s * (1.0f/4096.0f));
        }
    }
}

// ---------------- launch ----------------
extern "C" void kernel_launch(void* const* d_in, const int* in_sizes, int n_in,
                              void* d_out, int out_size) {
    const float* x  = (const float*)d_in[0];
    const float* wq = (const float*)d_in[1];
    const float* kv = (const float*)d_in[2];
    const float* wo = (const float*)d_in[3];
    const float* w1 = (const float*)d_in[4];
    const float* b1 = (const float*)d_in[5];
    const float* w2 = (const float*)d_in[6];
    const float* b2 = (const float*)d_in[7];
    float* out = (float*)d_out;

    const int SMEM = 67584;
    cudaFuncSetAttribute(fused_gemm<0, true >, cudaFuncAttributeMaxDynamicSharedMemorySize, SMEM);
    cudaFuncSetAttribute(fused_gemm<1, false>, cudaFuncAttributeMaxDynamicSharedMemorySize, SMEM);
    cudaFuncSetAttribute(fused_gemm<2, false>, cudaFuncAttributeMaxDynamicSharedMemorySize, SMEM);
    cudaFuncSetAttribute(fused_gemm<3, false>, cudaFuncAttributeMaxDynamicSharedMemorySize, SMEM);

    zero_out_kernel<<<128, 256>>>(out, BATCH * DIM);
    prep_A_kernel<<<dim3(16, 16), 256>>>(wq, kv);
    prep_B_kernel<<<dim3(16, 16), 256>>>(kv, wo);
    conv_w_kernel<<<4096, 256>>>(w1, w2);

    fused_gemm<0, true ><<<NBLOCKS, 256, SMEM>>>(x,       nullptr, nullptr);
    fused_gemm<1, false><<<NBLOCKS, 256, SMEM>>>(nullptr, nullptr, nullptr);
    fused_gemm<2, false><<<NBLOCKS, 256, SMEM>>>(nullptr, b1,      nullptr);
    fused_gemm<3, false><<<NBLOCKS, 256, SMEM>>>(nullptr, b2,      out);
}

// round 2
// speedup vs baseline: 1.5757x; 1.5757x over previous
#include <cuda_runtime.h>
#include <cuda_fp16.h>
#include <mma.h>

using namespace nvcuda;

// Problem constants
#define NTOK   131072          // B*S = 32*4096
#define DIM    1024
#define BATCH  32
#define SEQ    4096
#define NBLOCKS ((NTOK/128)*(DIM/128))  // 8192

// ---------------- device scratch ----------------
__device__ __half g_A  [1024*1024];            // logits weights: wq_h @ kv_h^T
__device__ __half g_Bm [1024*1024];            // kv_h @ wo_h
__device__ __half g_w1h[1024*1024];
__device__ __half g_w2h[1024*1024];
__device__ __half g_Xh [(size_t)NTOK*1024];    // x in fp16     (256MB)
__device__ __half g_P  [(size_t)NTOK*1024];    // softmax probs (256MB)
__device__ __half g_U  [(size_t)NTOK*1024];    // out@wo        (256MB)
__device__ __half g_H  [(size_t)NTOK*1024];    // gelu hidden   (256MB)

// ---------------- helpers ----------------
__global__ void zero_out_kernel(float* o, int n) {
    int i = blockIdx.x * 256 + threadIdx.x;
    if (i < n) o[i] = 0.0f;
}

// A[d, h*64+r] = sum_j wq[d, h*64+j] * kv[r, h*64+j]
__global__ void prep_A_kernel(const float* __restrict__ wq,
                              const float* __restrict__ kv) {
    __shared__ float wq_s[64][65];
    __shared__ float kv_s[64][65];
    int h  = blockIdx.x;
    int dt = blockIdx.y;
    int t  = threadIdx.x;
    #pragma unroll
    for (int e = 0; e < 16; e++) {
        int lin = t + 256 * e;
        int r = lin >> 6, c = lin & 63;
        wq_s[r][c] = wq[(size_t)(dt*64 + r)*1024 + h*64 + c];
        kv_s[r][c] = kv[(size_t)r*1024 + h*64 + c];
    }
    __syncthreads();
    #pragma unroll
    for (int e = 0; e < 16; e++) {
        int lin = t + 256 * e;
        int i = lin >> 6, r = lin & 63;
        float s = 0.f;
        #pragma unroll
        for (int j = 0; j < 64; j++) s += wq_s[i][j] * kv_s[r][j];
        g_A[(size_t)(dt*64 + i)*1024 + h*64 + r] = __float2half_rn(s);
    }
}

// Bm[h*64+r, d] = sum_j kv[r, h*64+j] * wo[h*64+j, d]
__global__ void prep_B_kernel(const float* __restrict__ kv,
                              const float* __restrict__ wo) {
    __shared__ float kv_s[64][65];
    __shared__ float wo_s[64][65];
    int h  = blockIdx.x;
    int ct = blockIdx.y;
    int t  = threadIdx.x;
    #pragma unroll
    for (int e = 0; e < 16; e++) {
        int lin = t + 256 * e;
        int r = lin >> 6, c = lin & 63;
        kv_s[r][c] = kv[(size_t)r*1024 + h*64 + c];
        wo_s[r][c] = wo[(size_t)(h*64 + r)*1024 + ct*64 + c];
    }
    __syncthreads();
    #pragma unroll
    for (int e = 0; e < 16; e++) {
        int lin = t + 256 * e;
        int r = lin >> 6, d = lin & 63;
        float s = 0.f;
        #pragma unroll
        for (int j = 0; j < 64; j++) s += kv_s[r][j] * wo_s[j][d];
        g_Bm[(size_t)(h*64 + r)*1024 + ct*64 + d] = __float2half_rn(s);
    }
}

__global__ void conv_w_kernel(const float* __restrict__ w1,
                              const float* __restrict__ w2) {
    int i = blockIdx.x * 256 + threadIdx.x;
    g_w1h[i] = __float2half_rn(w1[i]);
    g_w2h[i] = __float2half_rn(w2[i]);
}

// convert x (fp32 -> fp16), 8 elems per thread
__global__ void conv_x_kernel(const float* __restrict__ x) {
    size_t i = ((size_t)blockIdx.x * 256 + threadIdx.x) * 8;
    float4 a = *(const float4*)(x + i);
    float4 b = *(const float4*)(x + i + 4);
    union { uint4 u4; __half2 h2[4]; } pk;
    pk.h2[0] = __floats2half2_rn(a.x, a.y);
    pk.h2[1] = __floats2half2_rn(a.z, a.w);
    pk.h2[2] = __floats2half2_rn(b.x, b.y);
    pk.h2[3] = __floats2half2_rn(b.z, b.w);
    *(uint4*)(g_Xh + i) = pk.u4;
}

__device__ __forceinline__ void cpa16(void* dst, const void* src) {
    unsigned s = (unsigned)__cvta_generic_to_shared(dst);
    asm volatile("cp.async.cg.shared.global [%0], [%1], 16;\n" :: "r"(s), "l"(src));
}

// ---------------- fused GEMM (double-buffered cp.async) ----------------
// SMEM: two stages of {A[128x72] halves, W[64x136] halves} = 2 x 35840 B.
// Epilogue reuses smem as C_s float[128][132].
#define STAGE_BYTES 35840
#define SMEM_BYTES  (2*STAGE_BYTES)

template<int MODE>
__global__ void __launch_bounds__(256)
fused_gemm(const float* __restrict__ bias, float* __restrict__ outp) {
    extern __shared__ char smem[];
    float* C_s = (float*)smem;     // 128 x 132 floats = 67584 B (reuse)

    const __half* Ag;
    const __half* Wg;
    if constexpr (MODE == 0)      { Ag = g_Xh; Wg = g_A;   }
    else if constexpr (MODE == 1) { Ag = g_P;  Wg = g_Bm;  }
    else if constexpr (MODE == 2) { Ag = g_U;  Wg = g_w1h; }
    else                          { Ag = g_H;  Wg = g_w2h; }

    int t    = threadIdx.x;
    int bid  = blockIdx.x;
    int rt   = bid >> 3;
    int ct   = bid & 7;
    int row0 = rt * 128;
    int n0   = ct * 128;
    int warp = t >> 5;
    int wm   = warp & 3;       // 4 warp rows of 32
    int wn   = warp >> 2;      // 2 warp cols of 64

    wmma::fragment<wmma::accumulator, 16, 16, 16, float> acc[2][4];
    #pragma unroll
    for (int mi = 0; mi < 2; mi++)
        #pragma unroll
        for (int ni = 0; ni < 4; ni++)
            wmma::fill_fragment(acc[mi][ni], 0.0f);

    // stage one 64-wide K chunk into buffer `buf`
    auto stage = [&](int kc, int buf) {
        __half* A_s = (__half*)(smem + buf*STAGE_BYTES);
        __half* W_s = (__half*)(smem + buf*STAGE_BYTES + 18432);
        #pragma unroll
        for (int e = 0; e < 4; e++) {
            int lin = t + 256*e;
            int r = lin >> 3, sg = lin & 7;
            cpa16(A_s + r*72 + sg*8, Ag + (size_t)(row0 + r)*1024 + kc + sg*8);
        }
        #pragma unroll
        for (int e = 0; e < 4; e++) {
            int lin = t + 256*e;
            int r = lin >> 4, sg = lin & 15;
            cpa16(W_s + r*136 + sg*8, Wg + (size_t)(kc + r)*1024 + n0 + sg*8);
        }
        asm volatile("cp.async.commit_group;\n");
    };

    stage(0, 0);
    for (int k = 0; k < 16; k++) {
        if (k + 1 < 16) {
            stage((k+1)*64, (k+1) & 1);
            asm volatile("cp.async.wait_group 1;\n");
        } else {
            asm volatile("cp.async.wait_group 0;\n");
        }
        __syncthreads();

        const __half* A_s = (const __half*)(smem + (k&1)*STAGE_BYTES);
        const __half* W_s = (const __half*)(smem + (k&1)*STAGE_BYTES + 18432);
        #pragma unroll
        for (int kk = 0; kk < 64; kk += 16) {
            wmma::fragment<wmma::matrix_a, 16, 16, 16, __half, wmma::row_major> af[2];
            wmma::fragment<wmma::matrix_b, 16, 16, 16, __half, wmma::row_major> bf[4];
            #pragma unroll
            for (int mi = 0; mi < 2; mi++)
                wmma::load_matrix_sync(af[mi], A_s + (wm*32 + mi*16)*72 + kk, 72);
            #pragma unroll
            for (int ni = 0; ni < 4; ni++)
                wmma::load_matrix_sync(bf[ni], W_s + kk*136 + wn*64 + ni*16, 136);
            #pragma unroll
            for (int mi = 0; mi < 2; mi++)
                #pragma unroll
                for (int ni = 0; ni < 4; ni++)
                    wmma::mma_sync(acc[mi][ni], af[mi], bf[ni], acc[mi][ni]);
        }
        __syncthreads();   // all reads of buf (k&1) done before it is re-staged
    }

    // ---- dump accumulators to SMEM ----
    #pragma unroll
    for (int mi = 0; mi < 2; mi++)
        #pragma unroll
        for (int ni = 0; ni < 4; ni++)
            wmma::store_matrix_sync(C_s + (wm*32 + mi*16)*132 + wn*64 + ni*16,
                                    acc[mi][ni], 132, wmma::mem_row_major);
    __syncthreads();

    // ---- epilogues ----
    if constexpr (MODE == 0) {
        const float scale = 0.125f;                 // R^-0.5
        int row  = t >> 1;
        int head = t & 1;
        const float* rowp = C_s + row*132 + head*64;
        float m = -1e30f;
        #pragma unroll
        for (int j = 0; j < 64; j++) m = fmaxf(m, rowp[j] * scale);
        float s = 0.f;
        #pragma unroll
        for (int j = 0; j < 64; j++) s += __expf(rowp[j]*scale - m);
        float inv = 1.f / s;
        __half* op = g_P + (size_t)(row0 + row)*1024 + n0 + head*64;
        #pragma unroll
        for (int j = 0; j < 64; j += 8) {
            union { uint4 u4; __half2 h2[4]; } pk;
            #pragma unroll
            for (int q = 0; q < 4; q++) {
                float v0 = __expf(rowp[j + 2*q    ]*scale - m) * inv;
                float v1 = __expf(rowp[j + 2*q + 1]*scale - m) * inv;
                pk.h2[q] = __floats2half2_rn(v0, v1);
            }
            *(uint4*)(op + j) = pk.u4;
        }
    } else if constexpr (MODE == 1 || MODE == 2) {
        __half* dstbase = (MODE == 1) ? g_U : g_H;
        #pragma unroll
        for (int v = 0; v < 8; v++) {
            int lin = t + 256 * v;
            int i = lin >> 4, u = lin & 15;
            const float* src = C_s + i*132 + u*8;
            float vals[8];
            #pragma unroll
            for (int jj = 0; jj < 8; jj++) vals[jj] = src[jj];
            if constexpr (MODE == 2) {
                #pragma unroll
                for (int jj = 0; jj < 8; jj++) {
                    float z = vals[jj] + __ldg(bias + n0 + u*8 + jj);
                    vals[jj] = 0.5f * z * (1.0f + erff(z * 0.70710678118f));
                }
            }
            union { uint4 u4; __half2 h2[4]; } pk;
            #pragma unroll
            for (int q = 0; q < 4; q++)
                pk.h2[q] = __floats2half2_rn(vals[2*q], vals[2*q+1]);
            *(uint4*)(dstbase + (size_t)(row0 + i)*1024 + n0 + u*8) = pk.u4;
        }
    } else {
        // MODE 3: y = C + b2 + U residual; partial mean-pool over the 128 rows
        if (t < 128) {
            int gcol = n0 + t;
            float b2v = __ldg(bias + gcol);
            float s = 0.f;
            #pragma unroll 4
            for (int i = 0; i < 128; i++) {
                float u = __half2float(g_U[(size_t)(row0 + i)*1024 + gcol]);
                s += C_s[i*132 + t] + b2v + u;
            }
            int b = row0 >> 12;
            atomicAdd(outp + b*1024 + gcol, s * (1.0f/4096.0f));
        }
    }
}

// ---------------- launch ----------------
extern "C" void kernel_launch(void* const* d_in, const int* in_sizes, int n_in,
                              void* d_out, int out_size) {
    const float* x  = (const float*)d_in[0];
    const float* wq = (const float*)d_in[1];
    const float* kv = (const float*)d_in[2];
    const float* wo = (const float*)d_in[3];
    const float* w1 = (const float*)d_in[4];
    const float* b1 = (const float*)d_in[5];
    const float* w2 = (const float*)d_in[6];
    const float* b2 = (const float*)d_in[7];
    float* out = (float*)d_out;

    cudaFuncSetAttribute(fused_gemm<0>, cudaFuncAttributeMaxDynamicSharedMemorySize, SMEM_BYTES);
    cudaFuncSetAttribute(fused_gemm<1>, cudaFuncAttributeMaxDynamicSharedMemorySize, SMEM_BYTES);
    cudaFuncSetAttribute(fused_gemm<2>, cudaFuncAttributeMaxDynamicSharedMemorySize, SMEM_BYTES);
    cudaFuncSetAttribute(fused_gemm<3>, cudaFuncAttributeMaxDynamicSharedMemorySize, SMEM_BYTES);

    // launch order chosen so ncu -s 5 -c 1 captures fused_gemm<0>
    zero_out_kernel<<<128, 256>>>(out, BATCH * DIM);               // 1
    prep_A_kernel<<<dim3(16, 16), 256>>>(wq, kv);                  // 2
    prep_B_kernel<<<dim3(16, 16), 256>>>(kv, wo);                  // 3
    conv_w_kernel<<<4096, 256>>>(w1, w2);                          // 4
    conv_x_kernel<<<65536, 256>>>(x);                              // 5

    fused_gemm<0><<<NBLOCKS, 256, SMEM_BYTES>>>(nullptr, nullptr); // 6 <- profiled
    fused_gemm<1><<<NBLOCKS, 256, SMEM_BYTES>>>(nullptr, nullptr);
    fused_gemm<2><<<NBLOCKS, 256, SMEM_BYTES>>>(b1,      nullptr);
    fused_gemm<3><<<NBLOCKS, 256, SMEM_BYTES>>>(b2,      out);
}

// round 7
// speedup vs baseline: 1.5928x; 1.0108x over previous
#include <cuda_runtime.h>
#include <cuda_fp16.h>
#include <mma.h>

using namespace nvcuda;

// Problem constants
#define NTOK   131072          // B*S = 32*4096
#define DIM    1024
#define BATCH  32
#define SEQ    4096
#define NBLOCKS ((NTOK/128)*(DIM/128))  // 8192

// ---------------- device scratch ----------------
__device__ __half g_A  [1024*1024];            // logits weights: wq_h @ kv_h^T  [d][hr]
__device__ __half g_Bm [1024*1024];            // kv_h @ wo_h                   [hr][d]
__device__ __half g_w1h[1024*1024];            // w1 [k][n]
__device__ __half g_w2h[1024*1024];            // w2 [k][n]
__device__ __half g_Xh [(size_t)NTOK*1024];    // x in fp16     (256MB)
__device__ __half g_P  [(size_t)NTOK*1024];    // softmax probs (256MB)
__device__ __half g_U  [(size_t)NTOK*1024];    // out@wo        (256MB)
__device__ __half g_H  [(size_t)NTOK*1024];    // gelu hidden   (256MB)

// ---------------- helpers ----------------
__global__ void zero_out_kernel(float* o, int n) {
    int i = blockIdx.x * 256 + threadIdx.x;
    if (i < n) o[i] = 0.0f;
}

// A[d, h*64+r] = sum_j wq[d, h*64+j] * kv[r, h*64+j]
__global__ void prep_A_kernel(const float* __restrict__ wq,
                              const float* __restrict__ kv) {
    __shared__ float wq_s[64][65];
    __shared__ float kv_s[64][65];
    int h  = blockIdx.x;
    int dt = blockIdx.y;
    int t  = threadIdx.x;
    #pragma unroll
    for (int e = 0; e < 16; e++) {
        int lin = t + 256 * e;
        int r = lin >> 6, c = lin & 63;
        wq_s[r][c] = wq[(size_t)(dt*64 + r)*1024 + h*64 + c];
        kv_s[r][c] = kv[(size_t)r*1024 + h*64 + c];
    }
    __syncthreads();
    #pragma unroll
    for (int e = 0; e < 16; e++) {
        int lin = t + 256 * e;
        int i = lin >> 6, r = lin & 63;
        float s = 0.f;
        #pragma unroll
        for (int j = 0; j < 64; j++) s += wq_s[i][j] * kv_s[r][j];
        g_A[(size_t)(dt*64 + i)*1024 + h*64 + r] = __float2half_rn(s);
    }
}

// Bm[h*64+r, d] = sum_j kv[r, h*64+j] * wo[h*64+j, d]
__global__ void prep_B_kernel(const float* __restrict__ kv,
                              const float* __restrict__ wo) {
    __shared__ float kv_s[64][65];
    __shared__ float wo_s[64][65];
    int h  = blockIdx.x;
    int ct = blockIdx.y;
    int t  = threadIdx.x;
    #pragma unroll
    for (int e = 0; e < 16; e++) {
        int lin = t + 256 * e;
        int r = lin >> 6, c = lin & 63;
        kv_s[r][c] = kv[(size_t)r*1024 + h*64 + c];
        wo_s[r][c] = wo[(size_t)(h*64 + r)*1024 + ct*64 + c];
    }
    __syncthreads();
    #pragma unroll
    for (int e = 0; e < 16; e++) {
        int lin = t + 256 * e;
        int r = lin >> 6, d = lin & 63;
        float s = 0.f;
        #pragma unroll
        for (int j = 0; j < 64; j++) s += kv_s[r][j] * wo_s[j][d];
        g_Bm[(size_t)(h*64 + r)*1024 + ct*64 + d] = __float2half_rn(s);
    }
}

__global__ void conv_w_kernel(const float* __restrict__ w1,
                              const float* __restrict__ w2) {
    int i = blockIdx.x * 256 + threadIdx.x;
    g_w1h[i] = __float2half_rn(w1[i]);
    g_w2h[i] = __float2half_rn(w2[i]);
}

// convert x (fp32 -> fp16), 8 elems per thread
__global__ void conv_x_kernel(const float* __restrict__ x) {
    size_t i = ((size_t)blockIdx.x * 256 + threadIdx.x) * 8;
    float4 a = *(const float4*)(x + i);
    float4 b = *(const float4*)(x + i + 4);
    union { uint4 u4; __half2 h2[4]; } pk;
    pk.h2[0] = __floats2half2_rn(a.x, a.y);
    pk.h2[1] = __floats2half2_rn(a.z, a.w);
    pk.h2[2] = __floats2half2_rn(b.x, b.y);
    pk.h2[3] = __floats2half2_rn(b.z, b.w);
    *(uint4*)(g_Xh + i) = pk.u4;
}

__device__ __forceinline__ void cpa16(void* dst, const void* src) {
    unsigned s = (unsigned)__cvta_generic_to_shared(dst);
    asm volatile("cp.async.cg.shared.global [%0], [%1], 16;\n" :: "r"(s), "l"(src));
}

// ---------------- fused GEMM (3-stage cp.async, 1 sync/chunk) ----------------
// SMEM: three stages of {A[128x72] halves, W[64x136] halves} = 3 x 35840 B.
// Epilogue reuses smem as C_s float[128][132] (aliases stages 0-1).
#define STAGE_BYTES 35840
#define SMEM_BYTES  (3*STAGE_BYTES)

template<int MODE>
__global__ void __launch_bounds__(256)
fused_gemm(const float* __restrict__ bias, float* __restrict__ outp) {
    extern __shared__ char smem[];
    float* C_s = (float*)smem;     // 128 x 132 floats = 67584 B (reuse)

    const __half* Ag;
    const __half* Wg;
    if constexpr (MODE == 0)      { Ag = g_Xh; Wg = g_A;   }
    else if constexpr (MODE == 1) { Ag = g_P;  Wg = g_Bm;  }
    else if constexpr (MODE == 2) { Ag = g_U;  Wg = g_w1h; }
    else                          { Ag = g_H;  Wg = g_w2h; }

    int t    = threadIdx.x;
    int bid  = blockIdx.x;
    int rt   = bid >> 3;
    int ct   = bid & 7;
    int row0 = rt * 128;
    int n0   = ct * 128;
    int warp = t >> 5;
    int wm   = warp & 3;       // 4 warp rows of 32
    int wn   = warp >> 2;      // 2 warp cols of 64

    wmma::fragment<wmma::accumulator, 16, 16, 16, float> acc[2][4];
    #pragma unroll
    for (int mi = 0; mi < 2; mi++)
        #pragma unroll
        for (int ni = 0; ni < 4; ni++)
            wmma::fill_fragment(acc[mi][ni], 0.0f);

    // stage one 64-wide K chunk into buffer `buf`
    auto stage = [&](int kc, int buf) {
        __half* A_s = (__half*)(smem + buf*STAGE_BYTES);
        __half* W_s = (__half*)(smem + buf*STAGE_BYTES + 18432);
        #pragma unroll
        for (int e = 0; e < 4; e++) {
            int lin = t + 256*e;
            int r = lin >> 3, sg = lin & 7;
            cpa16(A_s + r*72 + sg*8, Ag + (size_t)(row0 + r)*1024 + kc + sg*8);
        }
        #pragma unroll
        for (int e = 0; e < 4; e++) {
            int lin = t + 256*e;
            int r = lin >> 4, sg = lin & 15;
            cpa16(W_s + r*136 + sg*8, Wg + (size_t)(kc + r)*1024 + n0 + sg*8);
        }
        asm volatile("cp.async.commit_group;\n");
    };

    // prologue: chunks 0 and 1
    stage(0, 0);
    stage(64, 1);

    for (int k = 0; k < 16; k++) {
        if (k < 15) asm volatile("cp.async.wait_group 1;\n");
        else        asm volatile("cp.async.wait_group 0;\n");
        __syncthreads();   // chunk k visible block-wide; slot (k+2)%3 readers (iter k-1) done

        if (k + 2 < 16) stage((k+2)*64, (k+2) % 3);

        int slot = k - (k/3)*3;
        const __half* A_s = (const __half*)(smem + slot*STAGE_BYTES);
        const __half* W_s = (const __half*)(smem + slot*STAGE_BYTES + 18432);
        #pragma unroll
        for (int kk = 0; kk < 64; kk += 16) {
            wmma::fragment<wmma::matrix_a, 16, 16, 16, __half, wmma::row_major> af[2];
            wmma::fragment<wmma::matrix_b, 16, 16, 16, __half, wmma::row_major> bf[4];
            #pragma unroll
            for (int mi = 0; mi < 2; mi++)
                wmma::load_matrix_sync(af[mi], A_s + (wm*32 + mi*16)*72 + kk, 72);
            #pragma unroll
            for (int ni = 0; ni < 4; ni++)
                wmma::load_matrix_sync(bf[ni], W_s + kk*136 + wn*64 + ni*16, 136);
            #pragma unroll
            for (int mi = 0; mi < 2; mi++)
                #pragma unroll
                for (int ni = 0; ni < 4; ni++)
                    wmma::mma_sync(acc[mi][ni], af[mi], bf[ni], acc[mi][ni]);
        }
    }
    __syncthreads();   // all smem reads done before C_s overwrite

    // ---- dump accumulators to SMEM ----
    #pragma unroll
    for (int mi = 0; mi < 2; mi++)
        #pragma unroll
        for (int ni = 0; ni < 4; ni++)
            wmma::store_matrix_sync(C_s + (wm*32 + mi*16)*132 + wn*64 + ni*16,
                                    acc[mi][ni], 132, wmma::mem_row_major);
    __syncthreads();

    // ---- epilogues ----
    if constexpr (MODE == 0) {
        const float scale = 0.125f;                 // R^-0.5
        int row  = t >> 1;
        int head = t & 1;
        const float* rowp = C_s + row*132 + head*64;
        float m = -1e30f;
        #pragma unroll
        for (int j = 0; j < 64; j++) m = fmaxf(m, rowp[j] * scale);
        float s = 0.f;
        #pragma unroll
        for (int j = 0; j < 64; j++) s += __expf(rowp[j]*scale - m);
        float inv = 1.f / s;
        __half* op = g_P + (size_t)(row0 + row)*1024 + n0 + head*64;
        #pragma unroll
        for (int j = 0; j < 64; j += 8) {
            union { uint4 u4; __half2 h2[4]; } pk;
            #pragma unroll
            for (int q = 0; q < 4; q++) {
                float v0 = __expf(rowp[j + 2*q    ]*scale - m) * inv;
                float v1 = __expf(rowp[j + 2*q + 1]*scale - m) * inv;
                pk.h2[q] = __floats2half2_rn(v0, v1);
            }
            *(uint4*)(op + j) = pk.u4;
        }
    } else if constexpr (MODE == 1 || MODE == 2) {
        __half* dstbase = (MODE == 1) ? g_U : g_H;
        #pragma unroll
        for (int v = 0; v < 8; v++) {
            int lin = t + 256 * v;
            int i = lin >> 4, u = lin & 15;
            const float* src = C_s + i*132 + u*8;
            float vals[8];
            #pragma unroll
            for (int jj = 0; jj < 8; jj++) vals[jj] = src[jj];
            if constexpr (MODE == 2) {
                #pragma unroll
                for (int jj = 0; jj < 8; jj++) {
                    float z = vals[jj] + __ldg(bias + n0 + u*8 + jj);
                    vals[jj] = 0.5f * z * (1.0f + erff(z * 0.70710678118f));
                }
            }
            union { uint4 u4; __half2 h2[4]; } pk;
            #pragma unroll
            for (int q = 0; q < 4; q++)
                pk.h2[q] = __floats2half2_rn(vals[2*q], vals[2*q+1]);
            *(uint4*)(dstbase + (size_t)(row0 + i)*1024 + n0 + u*8) = pk.u4;
        }
    } else {
        // MODE 3: y = C + b2 + U residual; partial mean-pool over the 128 rows
        if (t < 128) {
            int gcol = n0 + t;
            float b2v = __ldg(bias + gcol);
            float s = 0.f;
            #pragma unroll 4
            for (int i = 0; i < 128; i++) {
                float u = __half2float(g_U[(size_t)(row0 + i)*1024 + gcol]);
                s += C_s[i*132 + t] + b2v + u;
            }
            int b = row0 >> 12;
            atomicAdd(outp + b*1024 + gcol, s * (1.0f/4096.0f));
        }
    }
}

// ---------------- launch ----------------
extern "C" void kernel_launch(void* const* d_in, const int* in_sizes, int n_in,
                              void* d_out, int out_size) {
    const float* x  = (const float*)d_in[0];
    const float* wq = (const float*)d_in[1];
    const float* kv = (const float*)d_in[2];
    const float* wo = (const float*)d_in[3];
    const float* w1 = (const float*)d_in[4];
    const float* b1 = (const float*)d_in[5];
    const float* w2 = (const float*)d_in[6];
    const float* b2 = (const float*)d_in[7];
    float* out = (float*)d_out;

    cudaFuncSetAttribute(fused_gemm<0>, cudaFuncAttributeMaxDynamicSharedMemorySize, SMEM_BYTES);
    cudaFuncSetAttribute(fused_gemm<1>, cudaFuncAttributeMaxDynamicSharedMemorySize, SMEM_BYTES);
    cudaFuncSetAttribute(fused_gemm<2>, cudaFuncAttributeMaxDynamicSharedMemorySize, SMEM_BYTES);
    cudaFuncSetAttribute(fused_gemm<3>, cudaFuncAttributeMaxDynamicSharedMemorySize, SMEM_BYTES);

    zero_out_kernel<<<128, 256>>>(out, BATCH * DIM);
    prep_A_kernel<<<dim3(16, 16), 256>>>(wq, kv);
    prep_B_kernel<<<dim3(16, 16), 256>>>(kv, wo);
    conv_w_kernel<<<4096, 256>>>(w1, w2);
    conv_x_kernel<<<65536, 256>>>(x);

    fused_gemm<0><<<NBLOCKS, 256, SMEM_BYTES>>>(nullptr, nullptr);
    fused_gemm<1><<<NBLOCKS, 256, SMEM_BYTES>>>(nullptr, nullptr);
    fused_gemm<2><<<NBLOCKS, 256, SMEM_BYTES>>>(b1,      nullptr);
    fused_gemm<3><<<NBLOCKS, 256, SMEM_BYTES>>>(b2,      out);
}